// round 13
// baseline (speedup 1.0000x reference)
#include <cuda_runtime.h>
#include <cuda_fp16.h>
#include <cstdint>
#include <math.h>

#define NNODES 100000
#define NEDGES 3200000
#define NFEAT  256
#define NHID   128
#define NCLASS 40

#define SCAN_B  1024
#define SCAN_NB ((NNODES + SCAN_B - 1) / SCAN_B)   // 98

// ---------------- scratch ----------------
__device__ float  g_Self[(size_t)NNODES * NHID];
__device__ __half g_Ph[(size_t)NNODES * NHID];     // neighbor projection, fp16
__device__ float  g_H[(size_t)NNODES * NHID];
__device__ int    g_deg[NNODES];
__device__ int    g_rowptr[NNODES + 1];
__device__ int    g_cursor[NNODES];
__device__ int    g_colidx[NEDGES];
__device__ float  g_invdeg[NNODES];
__device__ int    g_blocksum[SCAN_NB];

// ---------------- CSR build ----------------
__global__ void k_zero_deg() {
    int i = blockIdx.x * blockDim.x + threadIdx.x;
    if (i < NNODES) g_deg[i] = 0;
}
__global__ void k_hist(const int* __restrict__ rows, int E) {
    int e = blockIdx.x * blockDim.x + threadIdx.x;
    if (e < E) atomicAdd(&g_deg[rows[e]], 1);
}

__global__ void k_scan1() {
    __shared__ int wsum[32];
    int tid = threadIdx.x, lane = tid & 31, wid = tid >> 5;
    int i = blockIdx.x * SCAN_B + tid;
    int v = (i < NNODES) ? g_deg[i] : 0;
    #pragma unroll
    for (int o = 16; o > 0; o >>= 1)
        v += __shfl_xor_sync(0xffffffffu, v, o);
    if (lane == 0) wsum[wid] = v;
    __syncthreads();
    if (wid == 0) {
        int y = wsum[lane];
        #pragma unroll
        for (int o = 16; o > 0; o >>= 1)
            y += __shfl_xor_sync(0xffffffffu, y, o);
        if (lane == 0) g_blocksum[blockIdx.x] = y;
    }
}

__global__ void k_scan2() {
    __shared__ int s[128];
    int tid = threadIdx.x;
    int v = (tid < SCAN_NB) ? g_blocksum[tid] : 0;
    s[tid] = v;
    __syncthreads();
    #pragma unroll
    for (int o = 1; o < 128; o <<= 1) {
        int t = (tid >= o) ? s[tid - o] : 0;
        __syncthreads();
        s[tid] += t;
        __syncthreads();
    }
    if (tid < SCAN_NB) g_blocksum[tid] = s[tid] - v;   // exclusive
    if (tid == 127) g_rowptr[NNODES] = s[127];
}

__global__ void k_scan3() {
    __shared__ int wsum[32];
    int tid = threadIdx.x, lane = tid & 31, wid = tid >> 5;
    int i = blockIdx.x * SCAN_B + tid;
    int v = (i < NNODES) ? g_deg[i] : 0;
    int x = v;
    #pragma unroll
    for (int o = 1; o < 32; o <<= 1) {
        int t = __shfl_up_sync(0xffffffffu, x, o);
        if (lane >= o) x += t;
    }
    if (lane == 31) wsum[wid] = x;
    __syncthreads();
    if (wid == 0) {
        int y = wsum[lane];
        #pragma unroll
        for (int o = 1; o < 32; o <<= 1) {
            int t = __shfl_up_sync(0xffffffffu, y, o);
            if (lane >= o) y += t;
        }
        wsum[lane] = y;
    }
    __syncthreads();
    if (i < NNODES) {
        int incl = x + (wid > 0 ? wsum[wid - 1] : 0) + g_blocksum[blockIdx.x];
        int excl = incl - v;
        g_rowptr[i] = excl;
        g_cursor[i] = excl;
        g_invdeg[i] = 1.0f / ((float)v + 1.0f);
    }
}

__global__ void k_scatter(const int* __restrict__ rows, const int* __restrict__ cols, int E) {
    int e = blockIdx.x * blockDim.x + threadIdx.x;
    if (e < E) {
        int r = rows[e];
        int p = atomicAdd(&g_cursor[r], 1);
        g_colidx[p] = cols[e];
    }
}

// ================= tf32 mma.sync GEMM, cp.async double-buffered =============
// y = blockIdx.y: 0 -> C0 fp32 (self slab of W), 1 -> C1h fp16 (neigh slab).
// Block: 256 thr / 8 warps; warp tile 32(m) x 64(n); K chunks of 32, 2 stages.
#define ABUF_F 4608            // 128*36 floats per stage
#define SMEM_FLOATS (4 * ABUF_F)
#define GEMM_SMEM_BYTES (SMEM_FLOATS * 4)

__global__ __launch_bounds__(256, 2) void mma_gemm_kernel(
    const float* __restrict__ A, const float* __restrict__ W,
    int K, int ldb,
    float* __restrict__ C0, __half* __restrict__ C1h, int Nrows)
{
    extern __shared__ float smemf[];   // [2][128][36] A, then [2][128][36] B
    const int tid = threadIdx.x;
    const int lane = tid & 31, wid = tid >> 5;
    const int warp_m = wid & 3;
    const int warp_n = wid >> 2;
    const int gid = lane >> 2, tig = lane & 3;
    const int tile0 = blockIdx.x * 128;
    const float* Bp = W + (size_t)blockIdx.y * K;
    const uint32_t smem_u32 = (uint32_t)__cvta_generic_to_shared(smemf);

    float acc[2][8][4];
    #pragma unroll
    for (int mi = 0; mi < 2; mi++)
        #pragma unroll
        for (int ni = 0; ni < 8; ni++)
            #pragma unroll
            for (int q = 0; q < 4; q++) acc[mi][ni][q] = 0.f;

    const int srow = tid >> 3;
    const int skq  = (tid & 7) << 2;
    int gr0 = tile0 + srow;

    auto stage = [&](int s, int kc) {
        #pragma unroll
        for (int it = 0; it < 4; it++) {
            int row = srow + (it << 5);
            int gr = gr0 + (it << 5);
            if (gr >= Nrows) gr = Nrows - 1;
            const float* ga = A + (size_t)gr * K + kc + skq;
            uint32_t da = smem_u32 + (uint32_t)((s * ABUF_F + row * 36 + skq) << 2);
            asm volatile("cp.async.ca.shared.global [%0], [%1], 16;" :: "r"(da), "l"(ga));
            const float* gb = Bp + (size_t)row * ldb + kc + skq;
            uint32_t db = smem_u32 + (uint32_t)(((2 * ABUF_F) + s * ABUF_F + row * 36 + skq) << 2);
            asm volatile("cp.async.ca.shared.global [%0], [%1], 16;" :: "r"(db), "l"(gb));
        }
        asm volatile("cp.async.commit_group;");
    };

    const int nch = K >> 5;
    stage(0, 0);

    for (int ch = 0; ch < nch; ch++) {
        const int s = ch & 1;
        if (ch + 1 < nch) {
            stage(s ^ 1, (ch + 1) << 5);
            asm volatile("cp.async.wait_group 1;");
        } else {
            asm volatile("cp.async.wait_group 0;");
        }
        __syncthreads();

        const float* Abuf = smemf + s * ABUF_F;
        const float* Bbuf = smemf + 2 * ABUF_F + s * ABUF_F;

        #pragma unroll
        for (int kb = 0; kb < 32; kb += 8) {
            uint32_t a[2][4];
            #pragma unroll
            for (int mi = 0; mi < 2; mi++) {
                int R = warp_m * 32 + mi * 16;
                a[mi][0] = __float_as_uint(Abuf[(R + gid) * 36 + kb + tig]);
                a[mi][1] = __float_as_uint(Abuf[(R + gid + 8) * 36 + kb + tig]);
                a[mi][2] = __float_as_uint(Abuf[(R + gid) * 36 + kb + tig + 4]);
                a[mi][3] = __float_as_uint(Abuf[(R + gid + 8) * 36 + kb + tig + 4]);
            }
            #pragma unroll
            for (int ni = 0; ni < 8; ni++) {
                int n0 = warp_n * 64 + ni * 8;
                uint32_t b0 = __float_as_uint(Bbuf[(n0 + gid) * 36 + kb + tig]);
                uint32_t b1 = __float_as_uint(Bbuf[(n0 + gid) * 36 + kb + tig + 4]);
                #pragma unroll
                for (int mi = 0; mi < 2; mi++) {
                    asm volatile(
                        "mma.sync.aligned.m16n8k8.row.col.f32.tf32.tf32.f32 "
                        "{%0,%1,%2,%3}, {%4,%5,%6,%7}, {%8,%9}, {%0,%1,%2,%3};"
                        : "+f"(acc[mi][ni][0]), "+f"(acc[mi][ni][1]),
                          "+f"(acc[mi][ni][2]), "+f"(acc[mi][ni][3])
                        : "r"(a[mi][0]), "r"(a[mi][1]), "r"(a[mi][2]), "r"(a[mi][3]),
                          "r"(b0), "r"(b1));
                }
            }
        }
        __syncthreads();
    }

    const bool half_out = (blockIdx.y != 0);
    #pragma unroll
    for (int mi = 0; mi < 2; mi++) {
        int r0 = tile0 + warp_m * 32 + mi * 16 + gid;
        #pragma unroll
        for (int ni = 0; ni < 8; ni++) {
            int c = warp_n * 64 + ni * 8 + tig * 2;
            if (half_out) {
                if (r0 < Nrows)
                    *reinterpret_cast<__half2*>(C1h + (size_t)r0 * 128 + c) =
                        __floats2half2_rn(acc[mi][ni][0], acc[mi][ni][1]);
                if (r0 + 8 < Nrows)
                    *reinterpret_cast<__half2*>(C1h + (size_t)(r0 + 8) * 128 + c) =
                        __floats2half2_rn(acc[mi][ni][2], acc[mi][ni][3]);
            } else {
                if (r0 < Nrows)
                    *reinterpret_cast<float2*>(C0 + (size_t)r0 * 128 + c) =
                        make_float2(acc[mi][ni][0], acc[mi][ni][1]);
                if (r0 + 8 < Nrows)
                    *reinterpret_cast<float2*>(C0 + (size_t)(r0 + 8) * 128 + c) =
                        make_float2(acc[mi][ni][2], acc[mi][ni][3]);
            }
        }
    }
}

// ---------------- CSR SpMM (fp16 gather) fused with SAGE epilogue -----------
// Layer 1: H[r] = relu(Self[r] + (sum Ph[c]) * invdeg[r])
__global__ void spmm_relu_kernel(const __half* __restrict__ P,
                                 const float* __restrict__ S,
                                 float* __restrict__ H)
{
    int warp = (blockIdx.x * blockDim.x + threadIdx.x) >> 5;
    int lane = threadIdx.x & 31;
    if (warp >= NNODES) return;
    int r = warp;
    int start = g_rowptr[r], end = g_rowptr[r + 1];

    float4 acc = make_float4(0.f, 0.f, 0.f, 0.f);
    for (int base = start; base < end; base += 32) {
        int idx = base + lane;
        int c = (idx < end) ? g_colidx[idx] : 0;
        int cnt = min(32, end - base);
        #pragma unroll 4
        for (int j = 0; j < cnt; j++) {
            int cj = __shfl_sync(0xffffffffu, c, j);
            uint2 raw = *reinterpret_cast<const uint2*>(P + (size_t)cj * 128 + lane * 4);
            float2 f0 = __half22float2(*reinterpret_cast<__half2*>(&raw.x));
            float2 f1 = __half22float2(*reinterpret_cast<__half2*>(&raw.y));
            acc.x += f0.x; acc.y += f0.y; acc.z += f1.x; acc.w += f1.y;
        }
    }
    float inv = g_invdeg[r];
    float4 s = *reinterpret_cast<const float4*>(S + (size_t)r * 128 + lane * 4);
    float4 h;
    h.x = fmaxf(fmaf(acc.x, inv, s.x), 0.f);
    h.y = fmaxf(fmaf(acc.y, inv, s.y), 0.f);
    h.z = fmaxf(fmaf(acc.z, inv, s.z), 0.f);
    h.w = fmaxf(fmaf(acc.w, inv, s.w), 0.f);
    *reinterpret_cast<float4*>(H + (size_t)r * 128 + lane * 4) = h;
}

// ====== Layer-2 SpMM fused with classifier + bias + log_softmax =============
// Per warp, per node: gather/epilogue exactly as spmm_relu, then h row ->
// per-warp smem, 40 fp32 dot-products vs block-shared W, warp-shuffle
// log_softmax, write out[node, 0:40]. H2 never touches gmem.
// Block: 256 thr / 8 warps; each warp handles 4 consecutive nodes.
#define CLSW 33   // float4 stride for padded smem rows (132 floats)

__global__ __launch_bounds__(256) void spmm_cls_kernel(
    const __half* __restrict__ P, const float* __restrict__ S,
    const float* __restrict__ W, const float* __restrict__ bias,
    float* __restrict__ out)
{
    __shared__ float4 sW[40 * CLSW];   // W padded: 21.1 KB
    __shared__ float4 sh[8 * CLSW];    // one h row per warp

    const int tid = threadIdx.x, lane = tid & 31, wid = tid >> 5;

    // Load W [40x128] into padded smem (1280 float4s, 5 per thread)
    #pragma unroll
    for (int i = 0; i < 5; i++) {
        int idx = tid + i * 256;
        int r = idx >> 5, q = idx & 31;
        sW[r * CLSW + q] = reinterpret_cast<const float4*>(W)[r * 32 + q];
    }
    __syncthreads();

    const float b1 = bias[lane];                         // class = lane (0..31)
    const float b2 = (lane < NCLASS - 32) ? bias[32 + lane] : 0.f;
    const float4* hrow = &sh[wid * CLSW];
    const float4* w1 = &sW[lane * CLSW];
    const float4* w2 = &sW[(32 + (lane & 7)) * CLSW];    // valid row; used if lane<8

    #pragma unroll 1
    for (int t = 0; t < 4; t++) {
        int node = blockIdx.x * 32 + wid * 4 + t;
        if (node >= NNODES) break;
        int start = g_rowptr[node], end = g_rowptr[node + 1];

        float4 acc = make_float4(0.f, 0.f, 0.f, 0.f);
        for (int base = start; base < end; base += 32) {
            int idx = base + lane;
            int c = (idx < end) ? g_colidx[idx] : 0;
            int cnt = min(32, end - base);
            #pragma unroll 4
            for (int j = 0; j < cnt; j++) {
                int cj = __shfl_sync(0xffffffffu, c, j);
                uint2 raw = *reinterpret_cast<const uint2*>(P + (size_t)cj * 128 + lane * 4);
                float2 f0 = __half22float2(*reinterpret_cast<__half2*>(&raw.x));
                float2 f1 = __half22float2(*reinterpret_cast<__half2*>(&raw.y));
                acc.x += f0.x; acc.y += f0.y; acc.z += f1.x; acc.w += f1.y;
            }
        }
        float inv = g_invdeg[node];
        float4 s4 = *reinterpret_cast<const float4*>(S + (size_t)node * 128 + lane * 4);
        float4 h;
        h.x = fmaxf(fmaf(acc.x, inv, s4.x), 0.f);
        h.y = fmaxf(fmaf(acc.y, inv, s4.y), 0.f);
        h.z = fmaxf(fmaf(acc.z, inv, s4.z), 0.f);
        h.w = fmaxf(fmaf(acc.w, inv, s4.w), 0.f);

        // stage h row (warp-private region)
        sh[wid * CLSW + lane] = h;
        __syncwarp();

        // two dot-products per lane (class lane, class 32+lane for lane<8)
        float d1 = 0.f, d2 = 0.f;
        #pragma unroll 8
        for (int kk = 0; kk < 32; kk++) {
            float4 hv = hrow[kk];
            float4 wa = w1[kk];
            d1 += hv.x * wa.x + hv.y * wa.y + hv.z * wa.z + hv.w * wa.w;
            float4 wb = w2[kk];
            d2 += hv.x * wb.x + hv.y * wb.y + hv.z * wb.z + hv.w * wb.w;
        }
        __syncwarp();

        float l1 = d1 + b1;
        float l2 = (lane < NCLASS - 32) ? d2 + b2 : -INFINITY;
        float mx = fmaxf(l1, l2);
        #pragma unroll
        for (int o = 16; o > 0; o >>= 1)
            mx = fmaxf(mx, __shfl_xor_sync(0xffffffffu, mx, o));
        float se = __expf(l1 - mx) + ((lane < NCLASS - 32) ? __expf(l2 - mx) : 0.f);
        #pragma unroll
        for (int o = 16; o > 0; o >>= 1)
            se += __shfl_xor_sync(0xffffffffu, se, o);
        float ls = mx + __logf(se);

        float* orow = out + (size_t)node * NCLASS;
        orow[lane] = l1 - ls;
        if (lane < NCLASS - 32) orow[32 + lane] = l2 - ls;
    }
}

// ---------------- launch ----------------
extern "C" void kernel_launch(void* const* d_in, const int* in_sizes, int n_in,
                              void* d_out, int out_size) {
    const float* x     = (const float*)d_in[0];   // [N,256]
    const float* W1    = (const float*)d_in[1];   // [128,512]
    const float* W2    = (const float*)d_in[2];   // [128,256]
    const float* mlpW  = (const float*)d_in[3];   // [40,128]
    const float* mlpb  = (const float*)d_in[4];   // [40]
    const int*   erow  = (const int*)d_in[5];
    const int*   ecol  = (const int*)d_in[6];
    int E = in_sizes[5];
    float* out = (float*)d_out;

    float *pSelf, *pH;
    __half* pPh;
    cudaGetSymbolAddress((void**)&pSelf, g_Self);
    cudaGetSymbolAddress((void**)&pPh, g_Ph);
    cudaGetSymbolAddress((void**)&pH, g_H);

    static cudaStream_t s_gemm = nullptr;
    static cudaEvent_t  ev_fork = nullptr, ev_join = nullptr;
    if (s_gemm == nullptr) {
        cudaStreamCreateWithFlags(&s_gemm, cudaStreamNonBlocking);
        cudaEventCreateWithFlags(&ev_fork, cudaEventDisableTiming);
        cudaEventCreateWithFlags(&ev_join, cudaEventDisableTiming);
        cudaFuncSetAttribute(mma_gemm_kernel,
                             cudaFuncAttributeMaxDynamicSharedMemorySize, GEMM_SMEM_BYTES);
    }

    const int nb_nodes = (NNODES + 255) / 256;
    const int nb_edges = (E + 255) / 256;
    const int nb_warps = (NNODES * 32 + 255) / 256;
    const int nb_tiles = (NNODES + 127) / 128;
    dim3 g1(nb_tiles, 2);

    // Fork: layer-1 GEMM on side stream, CSR build on main stream (independent)
    cudaEventRecord(ev_fork, 0);
    cudaStreamWaitEvent(s_gemm, ev_fork, 0);
    mma_gemm_kernel<<<g1, 256, GEMM_SMEM_BYTES, s_gemm>>>(x, W1, NFEAT, 2 * NFEAT,
                                                          pSelf, pPh, NNODES);
    cudaEventRecord(ev_join, s_gemm);

    k_zero_deg<<<nb_nodes, 256>>>();
    k_hist<<<nb_edges, 256>>>(erow, E);
    k_scan1<<<SCAN_NB, SCAN_B>>>();
    k_scan2<<<1, 128>>>();
    k_scan3<<<SCAN_NB, SCAN_B>>>();
    k_scatter<<<nb_edges, 256>>>(erow, ecol, E);

    // Join: SpMM needs both CSR and the layer-1 projections
    cudaStreamWaitEvent(0, ev_join, 0);
    spmm_relu_kernel<<<nb_warps, 256>>>(pPh, pSelf, pH);

    // Layer 2 GEMM
    mma_gemm_kernel<<<g1, 256, GEMM_SMEM_BYTES>>>(pH, W2, NHID, 2 * NHID,
                                                  pSelf, pPh, NNODES);

    // Layer-2 SpMM fused with classifier (H2 never hits gmem)
    spmm_cls_kernel<<<(NNODES + 31) / 32, 256>>>(pPh, pSelf, mlpW, mlpb, out);
}

// round 14
// speedup vs baseline: 1.6506x; 1.6506x over previous
#include <cuda_runtime.h>
#include <cuda_fp16.h>
#include <cstdint>
#include <math.h>

#define NNODES 100000
#define NEDGES 3200000
#define NFEAT  256
#define NHID   128
#define NCLASS 40

#define NH1 50048                     // half split: 391 tiles of 128
#define NH2 (NNODES - NH1)            // 49952

#define SCAN_B  1024
#define SCAN_NB ((NNODES + SCAN_B - 1) / SCAN_B)   // 98

// ---------------- scratch ----------------
__device__ float  g_Self[(size_t)NNODES * NHID];
__device__ __half g_Ph[(size_t)NNODES * NHID];     // neighbor projection, fp16
__device__ float  g_H[(size_t)NNODES * NHID];
__device__ int    g_deg[NNODES];
__device__ int    g_rowptr[NNODES + 1];
__device__ int    g_cursor[NNODES];
__device__ int    g_colidx[NEDGES];
__device__ float  g_invdeg[NNODES];
__device__ int    g_blocksum[SCAN_NB];

// ---------------- CSR build ----------------
__global__ void k_zero_deg() {
    int i = blockIdx.x * blockDim.x + threadIdx.x;
    if (i < NNODES) g_deg[i] = 0;
}
__global__ void k_hist(const int* __restrict__ rows, int E) {
    int e = blockIdx.x * blockDim.x + threadIdx.x;
    if (e < E) atomicAdd(&g_deg[rows[e]], 1);
}

__global__ void k_scan1() {
    __shared__ int wsum[32];
    int tid = threadIdx.x, lane = tid & 31, wid = tid >> 5;
    int i = blockIdx.x * SCAN_B + tid;
    int v = (i < NNODES) ? g_deg[i] : 0;
    #pragma unroll
    for (int o = 16; o > 0; o >>= 1)
        v += __shfl_xor_sync(0xffffffffu, v, o);
    if (lane == 0) wsum[wid] = v;
    __syncthreads();
    if (wid == 0) {
        int y = wsum[lane];
        #pragma unroll
        for (int o = 16; o > 0; o >>= 1)
            y += __shfl_xor_sync(0xffffffffu, y, o);
        if (lane == 0) g_blocksum[blockIdx.x] = y;
    }
}

__global__ void k_scan2() {
    __shared__ int s[128];
    int tid = threadIdx.x;
    int v = (tid < SCAN_NB) ? g_blocksum[tid] : 0;
    s[tid] = v;
    __syncthreads();
    #pragma unroll
    for (int o = 1; o < 128; o <<= 1) {
        int t = (tid >= o) ? s[tid - o] : 0;
        __syncthreads();
        s[tid] += t;
        __syncthreads();
    }
    if (tid < SCAN_NB) g_blocksum[tid] = s[tid] - v;   // exclusive
    if (tid == 127) g_rowptr[NNODES] = s[127];
}

__global__ void k_scan3() {
    __shared__ int wsum[32];
    int tid = threadIdx.x, lane = tid & 31, wid = tid >> 5;
    int i = blockIdx.x * SCAN_B + tid;
    int v = (i < NNODES) ? g_deg[i] : 0;
    int x = v;
    #pragma unroll
    for (int o = 1; o < 32; o <<= 1) {
        int t = __shfl_up_sync(0xffffffffu, x, o);
        if (lane >= o) x += t;
    }
    if (lane == 31) wsum[wid] = x;
    __syncthreads();
    if (wid == 0) {
        int y = wsum[lane];
        #pragma unroll
        for (int o = 1; o < 32; o <<= 1) {
            int t = __shfl_up_sync(0xffffffffu, y, o);
            if (lane >= o) y += t;
        }
        wsum[lane] = y;
    }
    __syncthreads();
    if (i < NNODES) {
        int incl = x + (wid > 0 ? wsum[wid - 1] : 0) + g_blocksum[blockIdx.x];
        int excl = incl - v;
        g_rowptr[i] = excl;
        g_cursor[i] = excl;
        g_invdeg[i] = 1.0f / ((float)v + 1.0f);
    }
}

__global__ void k_scatter(const int* __restrict__ rows, const int* __restrict__ cols, int E) {
    int e = blockIdx.x * blockDim.x + threadIdx.x;
    if (e < E) {
        int r = rows[e];
        int p = atomicAdd(&g_cursor[r], 1);
        g_colidx[p] = cols[e];
    }
}

// ================= tf32 mma.sync GEMM, cp.async double-buffered =============
// y = blockIdx.y: 0 -> C0 fp32 (self slab of W), 1 -> C1h fp16 (neigh slab).
// Block: 256 thr / 8 warps; warp tile 32(m) x 64(n); K chunks of 32, 2 stages.
// row_off: first A/C row handled by tile 0 (for half-split scheduling).
#define ABUF_F 4608            // 128*36 floats per stage
#define SMEM_FLOATS (4 * ABUF_F)
#define GEMM_SMEM_BYTES (SMEM_FLOATS * 4)

__global__ __launch_bounds__(256, 2) void mma_gemm_kernel(
    const float* __restrict__ A, const float* __restrict__ W,
    int K, int ldb, int row_off,
    float* __restrict__ C0, __half* __restrict__ C1h, int Nrows)
{
    extern __shared__ float smemf[];   // [2][128][36] A, then [2][128][36] B
    const int tid = threadIdx.x;
    const int lane = tid & 31, wid = tid >> 5;
    const int warp_m = wid & 3;
    const int warp_n = wid >> 2;
    const int gid = lane >> 2, tig = lane & 3;
    const int tile0 = row_off + blockIdx.x * 128;
    const float* Bp = W + (size_t)blockIdx.y * K;
    const uint32_t smem_u32 = (uint32_t)__cvta_generic_to_shared(smemf);

    float acc[2][8][4];
    #pragma unroll
    for (int mi = 0; mi < 2; mi++)
        #pragma unroll
        for (int ni = 0; ni < 8; ni++)
            #pragma unroll
            for (int q = 0; q < 4; q++) acc[mi][ni][q] = 0.f;

    const int srow = tid >> 3;
    const int skq  = (tid & 7) << 2;
    int gr0 = tile0 + srow;

    auto stage = [&](int s, int kc) {
        #pragma unroll
        for (int it = 0; it < 4; it++) {
            int row = srow + (it << 5);
            int gr = gr0 + (it << 5);
            if (gr >= Nrows) gr = Nrows - 1;
            const float* ga = A + (size_t)gr * K + kc + skq;
            uint32_t da = smem_u32 + (uint32_t)((s * ABUF_F + row * 36 + skq) << 2);
            asm volatile("cp.async.ca.shared.global [%0], [%1], 16;" :: "r"(da), "l"(ga));
            const float* gb = Bp + (size_t)row * ldb + kc + skq;
            uint32_t db = smem_u32 + (uint32_t)(((2 * ABUF_F) + s * ABUF_F + row * 36 + skq) << 2);
            asm volatile("cp.async.ca.shared.global [%0], [%1], 16;" :: "r"(db), "l"(gb));
        }
        asm volatile("cp.async.commit_group;");
    };

    const int nch = K >> 5;
    stage(0, 0);

    for (int ch = 0; ch < nch; ch++) {
        const int s = ch & 1;
        if (ch + 1 < nch) {
            stage(s ^ 1, (ch + 1) << 5);
            asm volatile("cp.async.wait_group 1;");
        } else {
            asm volatile("cp.async.wait_group 0;");
        }
        __syncthreads();

        const float* Abuf = smemf + s * ABUF_F;
        const float* Bbuf = smemf + 2 * ABUF_F + s * ABUF_F;

        #pragma unroll
        for (int kb = 0; kb < 32; kb += 8) {
            uint32_t a[2][4];
            #pragma unroll
            for (int mi = 0; mi < 2; mi++) {
                int R = warp_m * 32 + mi * 16;
                a[mi][0] = __float_as_uint(Abuf[(R + gid) * 36 + kb + tig]);
                a[mi][1] = __float_as_uint(Abuf[(R + gid + 8) * 36 + kb + tig]);
                a[mi][2] = __float_as_uint(Abuf[(R + gid) * 36 + kb + tig + 4]);
                a[mi][3] = __float_as_uint(Abuf[(R + gid + 8) * 36 + kb + tig + 4]);
            }
            #pragma unroll
            for (int ni = 0; ni < 8; ni++) {
                int n0 = warp_n * 64 + ni * 8;
                uint32_t b0 = __float_as_uint(Bbuf[(n0 + gid) * 36 + kb + tig]);
                uint32_t b1 = __float_as_uint(Bbuf[(n0 + gid) * 36 + kb + tig + 4]);
                #pragma unroll
                for (int mi = 0; mi < 2; mi++) {
                    asm volatile(
                        "mma.sync.aligned.m16n8k8.row.col.f32.tf32.tf32.f32 "
                        "{%0,%1,%2,%3}, {%4,%5,%6,%7}, {%8,%9}, {%0,%1,%2,%3};"
                        : "+f"(acc[mi][ni][0]), "+f"(acc[mi][ni][1]),
                          "+f"(acc[mi][ni][2]), "+f"(acc[mi][ni][3])
                        : "r"(a[mi][0]), "r"(a[mi][1]), "r"(a[mi][2]), "r"(a[mi][3]),
                          "r"(b0), "r"(b1));
                }
            }
        }
        __syncthreads();
    }

    const bool half_out = (blockIdx.y != 0);
    #pragma unroll
    for (int mi = 0; mi < 2; mi++) {
        int r0 = tile0 + warp_m * 32 + mi * 16 + gid;
        #pragma unroll
        for (int ni = 0; ni < 8; ni++) {
            int c = warp_n * 64 + ni * 8 + tig * 2;
            if (half_out) {
                if (r0 < Nrows)
                    *reinterpret_cast<__half2*>(C1h + (size_t)r0 * 128 + c) =
                        __floats2half2_rn(acc[mi][ni][0], acc[mi][ni][1]);
                if (r0 + 8 < Nrows)
                    *reinterpret_cast<__half2*>(C1h + (size_t)(r0 + 8) * 128 + c) =
                        __floats2half2_rn(acc[mi][ni][2], acc[mi][ni][3]);
            } else {
                if (r0 < Nrows)
                    *reinterpret_cast<float2*>(C0 + (size_t)r0 * 128 + c) =
                        make_float2(acc[mi][ni][0], acc[mi][ni][1]);
                if (r0 + 8 < Nrows)
                    *reinterpret_cast<float2*>(C0 + (size_t)(r0 + 8) * 128 + c) =
                        make_float2(acc[mi][ni][2], acc[mi][ni][3]);
            }
        }
    }
}

// ---------------- CSR SpMM (fp16 gather) fused with SAGE epilogue -----------
// H[r] = relu(Self[r] + (sum Ph[c]) * invdeg[r]); nodes [node_off, node_off+cnt)
__global__ void spmm_relu_kernel(const __half* __restrict__ P,
                                 const float* __restrict__ S,
                                 float* __restrict__ H,
                                 int node_off, int node_cnt)
{
    int warp = (blockIdx.x * blockDim.x + threadIdx.x) >> 5;
    int lane = threadIdx.x & 31;
    if (warp >= node_cnt) return;
    int r = node_off + warp;
    int start = g_rowptr[r], end = g_rowptr[r + 1];

    float4 acc = make_float4(0.f, 0.f, 0.f, 0.f);
    for (int base = start; base < end; base += 32) {
        int idx = base + lane;
        int c = (idx < end) ? g_colidx[idx] : 0;
        int cnt = min(32, end - base);
        #pragma unroll 4
        for (int j = 0; j < cnt; j++) {
            int cj = __shfl_sync(0xffffffffu, c, j);
            uint2 raw = *reinterpret_cast<const uint2*>(P + (size_t)cj * 128 + lane * 4);
            float2 f0 = __half22float2(*reinterpret_cast<__half2*>(&raw.x));
            float2 f1 = __half22float2(*reinterpret_cast<__half2*>(&raw.y));
            acc.x += f0.x; acc.y += f0.y; acc.z += f1.x; acc.w += f1.y;
        }
    }
    float inv = g_invdeg[r];
    float4 s = *reinterpret_cast<const float4*>(S + (size_t)r * 128 + lane * 4);
    float4 h;
    h.x = fmaxf(fmaf(acc.x, inv, s.x), 0.f);
    h.y = fmaxf(fmaf(acc.y, inv, s.y), 0.f);
    h.z = fmaxf(fmaf(acc.z, inv, s.z), 0.f);
    h.w = fmaxf(fmaf(acc.w, inv, s.w), 0.f);
    *reinterpret_cast<float4*>(H + (size_t)r * 128 + lane * 4) = h;
}

// ---------------- Classifier GEMM fused with bias + log_softmax (R8) --------
__global__ __launch_bounds__(256, 2) void cls_kernel(
    const float* __restrict__ A, const float* __restrict__ W,
    const float* __restrict__ bias, float* __restrict__ out,
    int node_off, int Nrows)
{
    __shared__ float As[8][128];
    __shared__ float Bs[8][64];

    int tid = threadIdx.x;
    int n0 = node_off + blockIdx.x * 128;
    int tx = tid & 15, ty = tid >> 4;

    float acc[8][4];
    #pragma unroll
    for (int i = 0; i < 8; i++)
        #pragma unroll
        for (int j = 0; j < 4; j++) acc[i][j] = 0.f;

    int aRow = tid >> 1;
    int aCol = (tid & 1) * 4;
    bool aValid = (n0 + aRow) < Nrows;
    const float* Aptr = A + (size_t)(n0 + aRow) * NHID + aCol;

    int bRow = tid >> 1;
    int bCol = (tid & 1) * 4;
    const float* Bptr = (tid < 128 && bRow < NCLASS) ? W + (size_t)bRow * NHID + bCol : nullptr;

    for (int k0 = 0; k0 < NHID; k0 += 8) {
        float4 av = aValid ? *reinterpret_cast<const float4*>(Aptr + k0)
                           : make_float4(0.f, 0.f, 0.f, 0.f);
        As[aCol + 0][aRow] = av.x; As[aCol + 1][aRow] = av.y;
        As[aCol + 2][aRow] = av.z; As[aCol + 3][aRow] = av.w;
        if (tid < 128) {
            float4 bv = Bptr ? *reinterpret_cast<const float4*>(Bptr + k0)
                             : make_float4(0.f, 0.f, 0.f, 0.f);
            Bs[bCol + 0][bRow] = bv.x; Bs[bCol + 1][bRow] = bv.y;
            Bs[bCol + 2][bRow] = bv.z; Bs[bCol + 3][bRow] = bv.w;
        }
        __syncthreads();

        #pragma unroll
        for (int k = 0; k < 8; k++) {
            float a[8], b[4];
            *reinterpret_cast<float4*>(a)     = *reinterpret_cast<float4*>(&As[k][ty * 8]);
            *reinterpret_cast<float4*>(a + 4) = *reinterpret_cast<float4*>(&As[k][ty * 8 + 4]);
            *reinterpret_cast<float4*>(b)     = *reinterpret_cast<float4*>(&Bs[k][tx * 4]);
            #pragma unroll
            for (int i = 0; i < 8; i++)
                #pragma unroll
                for (int j = 0; j < 4; j++)
                    acc[i][j] = fmaf(a[i], b[j], acc[i][j]);
        }
        __syncthreads();
    }

    float bs[4];
    #pragma unroll
    for (int j = 0; j < 4; j++) {
        int c = tx * 4 + j;
        bs[j] = (c < NCLASS) ? bias[c] : 0.f;
    }

    #pragma unroll
    for (int i = 0; i < 8; i++) {
        int row = n0 + ty * 8 + i;
        float l[4];
        #pragma unroll
        for (int j = 0; j < 4; j++) {
            int c = tx * 4 + j;
            l[j] = (c < NCLASS) ? acc[i][j] + bs[j] : -INFINITY;
        }
        float mx = fmaxf(fmaxf(l[0], l[1]), fmaxf(l[2], l[3]));
        #pragma unroll
        for (int o = 8; o > 0; o >>= 1)
            mx = fmaxf(mx, __shfl_xor_sync(0xffffffffu, mx, o));
        float se = 0.f;
        #pragma unroll
        for (int j = 0; j < 4; j++) {
            int c = tx * 4 + j;
            if (c < NCLASS) se += __expf(l[j] - mx);
        }
        #pragma unroll
        for (int o = 8; o > 0; o >>= 1)
            se += __shfl_xor_sync(0xffffffffu, se, o);
        float ls = mx + __logf(se);
        if (row < Nrows) {
            #pragma unroll
            for (int j = 0; j < 4; j++) {
                int c = tx * 4 + j;
                if (c < NCLASS) out[(size_t)row * NCLASS + c] = l[j] - ls;
            }
        }
    }
}

// ---------------- launch ----------------
extern "C" void kernel_launch(void* const* d_in, const int* in_sizes, int n_in,
                              void* d_out, int out_size) {
    const float* x     = (const float*)d_in[0];   // [N,256]
    const float* W1    = (const float*)d_in[1];   // [128,512]
    const float* W2    = (const float*)d_in[2];   // [128,256]
    const float* mlpW  = (const float*)d_in[3];   // [40,128]
    const float* mlpb  = (const float*)d_in[4];   // [40]
    const int*   erow  = (const int*)d_in[5];
    const int*   ecol  = (const int*)d_in[6];
    int E = in_sizes[5];
    float* out = (float*)d_out;

    float *pSelf, *pH;
    __half* pPh;
    cudaGetSymbolAddress((void**)&pSelf, g_Self);
    cudaGetSymbolAddress((void**)&pPh, g_Ph);
    cudaGetSymbolAddress((void**)&pH, g_H);

    static cudaStream_t s2 = nullptr;
    static cudaEvent_t ev_fork = nullptr, ev_join = nullptr,
                       ev_a = nullptr, ev_c = nullptr, ev_e = nullptr, ev_g = nullptr;
    if (s2 == nullptr) {
        cudaStreamCreateWithFlags(&s2, cudaStreamNonBlocking);
        cudaEventCreateWithFlags(&ev_fork, cudaEventDisableTiming);
        cudaEventCreateWithFlags(&ev_join, cudaEventDisableTiming);
        cudaEventCreateWithFlags(&ev_a, cudaEventDisableTiming);
        cudaEventCreateWithFlags(&ev_c, cudaEventDisableTiming);
        cudaEventCreateWithFlags(&ev_e, cudaEventDisableTiming);
        cudaEventCreateWithFlags(&ev_g, cudaEventDisableTiming);
        cudaFuncSetAttribute(mma_gemm_kernel,
                             cudaFuncAttributeMaxDynamicSharedMemorySize, GEMM_SMEM_BYTES);
    }

    const int nb_nodes = (NNODES + 255) / 256;
    const int nb_edges = (E + 255) / 256;
    const int nb_tiles_full = (NNODES + 127) / 128;        // 782
    const int nb_tiles_h1 = NH1 / 128;                     // 391
    const int nb_tiles_h2 = (NH2 + 127) / 128;             // 391
    const int nb_warps_h1 = (NH1 * 32 + 255) / 256;
    const int nb_warps_h2 = (NH2 * 32 + 255) / 256;

    // ---- Fork: full layer-1 GEMM on s2, CSR build on main (independent) ----
    cudaEventRecord(ev_fork, 0);
    cudaStreamWaitEvent(s2, ev_fork, 0);
    {
        dim3 g(nb_tiles_full, 2);
        mma_gemm_kernel<<<g, 256, GEMM_SMEM_BYTES, s2>>>(
            x, W1, NFEAT, 2 * NFEAT, 0, pSelf, pPh, NNODES);
    }
    cudaEventRecord(ev_join, s2);

    k_zero_deg<<<nb_nodes, 256>>>();
    k_hist<<<nb_edges, 256>>>(erow, E);
    k_scan1<<<SCAN_NB, SCAN_B>>>();
    k_scan2<<<1, 128>>>();
    k_scan3<<<SCAN_NB, SCAN_B>>>();
    k_scatter<<<nb_edges, 256>>>(erow, ecol, E);

    // ---- Join, then pipelined halves ----
    cudaStreamWaitEvent(0, ev_join, 0);

    // spmm1 half 1 (main), then gemm2_h1 (s2) overlaps spmm1 half 2 (main)
    spmm_relu_kernel<<<nb_warps_h1, 256>>>(pPh, pSelf, pH, 0, NH1);
    cudaEventRecord(ev_a, 0);
    cudaStreamWaitEvent(s2, ev_a, 0);
    {
        dim3 g(nb_tiles_h1, 2);
        mma_gemm_kernel<<<g, 256, GEMM_SMEM_BYTES, s2>>>(
            pH, W2, NHID, 2 * NHID, 0, pSelf, pPh, NNODES);
    }
    cudaEventRecord(ev_c, s2);

    spmm_relu_kernel<<<nb_warps_h2, 256>>>(pPh, pSelf, pH, NH1, NH2);
    {
        dim3 g(nb_tiles_h2, 2);
        mma_gemm_kernel<<<g, 256, GEMM_SMEM_BYTES>>>(
            pH, W2, NHID, 2 * NHID, NH1, pSelf, pPh, NNODES);
    }

    // spmm2 needs BOTH gemm2 halves (gather reads arbitrary Ph rows)
    cudaStreamWaitEvent(0, ev_c, 0);

    // spmm2 half 1 (main), then cls_h1 (s2) overlaps spmm2 half 2 (main)
    spmm_relu_kernel<<<nb_warps_h1, 256>>>(pPh, pSelf, pH, 0, NH1);
    cudaEventRecord(ev_e, 0);
    cudaStreamWaitEvent(s2, ev_e, 0);
    cls_kernel<<<nb_tiles_h1, 256, 0, s2>>>(pH, mlpW, mlpb, out, 0, NNODES);
    cudaEventRecord(ev_g, s2);

    spmm_relu_kernel<<<nb_warps_h2, 256>>>(pPh, pSelf, pH, NH1, NH2);
    cls_kernel<<<nb_tiles_h2, 256>>>(pH, mlpW, mlpb, out, NH1, NNODES);

    // join side stream back before capture ends
    cudaStreamWaitEvent(0, ev_g, 0);
}

// round 15
// speedup vs baseline: 1.7520x; 1.0615x over previous
#include <cuda_runtime.h>
#include <cuda_fp16.h>
#include <cstdint>
#include <math.h>

#define NNODES 100000
#define NEDGES 3200000
#define NFEAT  256
#define NHID   128
#define NCLASS 40

#define SCAN_B  1024
#define SCAN_NB ((NNODES + SCAN_B - 1) / SCAN_B)   // 98

// ---------------- scratch ----------------
__device__ float  g_Self[(size_t)NNODES * NHID];
__device__ __half g_Ph[(size_t)NNODES * NHID];      // neighbor projection, fp16
__device__ __half g_H[(size_t)NNODES * NHID];       // hidden activations, fp16
__device__ __half g_xh[(size_t)NNODES * NFEAT];     // fp16 copy of x
__device__ __half g_W1h[NHID * 2 * NFEAT];
__device__ __half g_W2h[NHID * 2 * NHID];
__device__ int    g_deg[NNODES];
__device__ int    g_rowptr[NNODES + 1];
__device__ int    g_cursor[NNODES];
__device__ int    g_colidx[NEDGES];
__device__ float  g_invdeg[NNODES];
__device__ int    g_blocksum[SCAN_NB];

// ---------------- fp32 -> fp16 convert (vectorized) ----------------
__global__ void k_cvt(const float* __restrict__ src, __half* __restrict__ dst, int n4) {
    int i = blockIdx.x * blockDim.x + threadIdx.x;
    if (i < n4) {
        float4 v = reinterpret_cast<const float4*>(src)[i];
        uint2 o;
        *reinterpret_cast<__half2*>(&o.x) = __floats2half2_rn(v.x, v.y);
        *reinterpret_cast<__half2*>(&o.y) = __floats2half2_rn(v.z, v.w);
        reinterpret_cast<uint2*>(dst)[i] = o;
    }
}

// ---------------- CSR build ----------------
__global__ void k_zero_deg() {
    int i = blockIdx.x * blockDim.x + threadIdx.x;
    if (i < NNODES) g_deg[i] = 0;
}
__global__ void k_hist(const int* __restrict__ rows, int E) {
    int e = blockIdx.x * blockDim.x + threadIdx.x;
    if (e < E) atomicAdd(&g_deg[rows[e]], 1);
}

__global__ void k_scan1() {
    __shared__ int wsum[32];
    int tid = threadIdx.x, lane = tid & 31, wid = tid >> 5;
    int i = blockIdx.x * SCAN_B + tid;
    int v = (i < NNODES) ? g_deg[i] : 0;
    #pragma unroll
    for (int o = 16; o > 0; o >>= 1)
        v += __shfl_xor_sync(0xffffffffu, v, o);
    if (lane == 0) wsum[wid] = v;
    __syncthreads();
    if (wid == 0) {
        int y = wsum[lane];
        #pragma unroll
        for (int o = 16; o > 0; o >>= 1)
            y += __shfl_xor_sync(0xffffffffu, y, o);
        if (lane == 0) g_blocksum[blockIdx.x] = y;
    }
}

__global__ void k_scan2() {
    __shared__ int s[128];
    int tid = threadIdx.x;
    int v = (tid < SCAN_NB) ? g_blocksum[tid] : 0;
    s[tid] = v;
    __syncthreads();
    #pragma unroll
    for (int o = 1; o < 128; o <<= 1) {
        int t = (tid >= o) ? s[tid - o] : 0;
        __syncthreads();
        s[tid] += t;
        __syncthreads();
    }
    if (tid < SCAN_NB) g_blocksum[tid] = s[tid] - v;   // exclusive
    if (tid == 127) g_rowptr[NNODES] = s[127];
}

__global__ void k_scan3() {
    __shared__ int wsum[32];
    int tid = threadIdx.x, lane = tid & 31, wid = tid >> 5;
    int i = blockIdx.x * SCAN_B + tid;
    int v = (i < NNODES) ? g_deg[i] : 0;
    int x = v;
    #pragma unroll
    for (int o = 1; o < 32; o <<= 1) {
        int t = __shfl_up_sync(0xffffffffu, x, o);
        if (lane >= o) x += t;
    }
    if (lane == 31) wsum[wid] = x;
    __syncthreads();
    if (wid == 0) {
        int y = wsum[lane];
        #pragma unroll
        for (int o = 1; o < 32; o <<= 1) {
            int t = __shfl_up_sync(0xffffffffu, y, o);
            if (lane >= o) y += t;
        }
        wsum[lane] = y;
    }
    __syncthreads();
    if (i < NNODES) {
        int incl = x + (wid > 0 ? wsum[wid - 1] : 0) + g_blocksum[blockIdx.x];
        int excl = incl - v;
        g_rowptr[i] = excl;
        g_cursor[i] = excl;
        g_invdeg[i] = 1.0f / ((float)v + 1.0f);
    }
}

__global__ void k_scatter(const int* __restrict__ rows, const int* __restrict__ cols, int E) {
    int e = blockIdx.x * blockDim.x + threadIdx.x;
    if (e < E) {
        int r = rows[e];
        int p = atomicAdd(&g_cursor[r], 1);
        g_colidx[p] = cols[e];
    }
}

// ================= fp16 mma.sync m16n8k16 GEMM, cp.async 2-stage ============
// y = blockIdx.y: 0 -> C0 fp32 (self slab of W), 1 -> C1h fp16 (neigh slab).
// A [Nrows, K] fp16; W [128, ldb] fp16, slab at col y*K.
// Block: 256 thr / 8 warps; warp tile 32(m) x 64(n); K chunks of 32, 2 stages.
// smem rows: 32 halves data + 8 pad = 40 halves (20 words == 4 mod 32:
// fragment LDS banks = 4*gid + tig + c -> conflict-free).
#define SHW 40                          // halves per smem row
#define STAGE_B (128 * SHW * 2)         // 10240 bytes per stage (A or B)
#define GEMM_SMEM_BYTES (4 * STAGE_B)   // 40960

__global__ __launch_bounds__(256, 2) void mma_gemm_fp16(
    const __half* __restrict__ A, const __half* __restrict__ W,
    int K, int ldb,
    float* __restrict__ C0, __half* __restrict__ C1h, int Nrows)
{
    extern __shared__ char smem[];
    __half* smh = reinterpret_cast<__half*>(smem);
    const int tid = threadIdx.x;
    const int lane = tid & 31, wid = tid >> 5;
    const int warp_m = wid & 3;
    const int warp_n = wid >> 2;
    const int gid = lane >> 2, tig = lane & 3;
    const int tile0 = blockIdx.x * 128;
    const __half* Bp = W + (size_t)blockIdx.y * K;
    const uint32_t smem_u32 = (uint32_t)__cvta_generic_to_shared(smem);

    float acc[2][8][4];
    #pragma unroll
    for (int mi = 0; mi < 2; mi++)
        #pragma unroll
        for (int ni = 0; ni < 8; ni++)
            #pragma unroll
            for (int q = 0; q < 4; q++) acc[mi][ni][q] = 0.f;

    // staging: 128 rows x 32 halves = 512 x 16B chunks per matrix, 2/thread
    const int srow = tid >> 2;          // +64 per it
    const int sc   = (tid & 3) << 3;    // halves offset within row (0,8,16,24)

    auto stage = [&](int s, int kc) {
        #pragma unroll
        for (int it = 0; it < 2; it++) {
            int row = srow + (it << 6);
            int gr = tile0 + row;
            if (gr >= Nrows) gr = Nrows - 1;
            const __half* ga = A + (size_t)gr * K + kc + sc;
            uint32_t da = smem_u32 + (uint32_t)(s * STAGE_B + row * (SHW * 2) + sc * 2);
            asm volatile("cp.async.ca.shared.global [%0], [%1], 16;" :: "r"(da), "l"(ga));
            const __half* gb = Bp + (size_t)row * ldb + kc + sc;
            uint32_t db = smem_u32 + (uint32_t)(2 * STAGE_B + s * STAGE_B + row * (SHW * 2) + sc * 2);
            asm volatile("cp.async.ca.shared.global [%0], [%1], 16;" :: "r"(db), "l"(gb));
        }
        asm volatile("cp.async.commit_group;");
    };

    const int nch = K >> 5;
    stage(0, 0);

    for (int ch = 0; ch < nch; ch++) {
        const int s = ch & 1;
        if (ch + 1 < nch) {
            stage(s ^ 1, (ch + 1) << 5);
            asm volatile("cp.async.wait_group 1;");
        } else {
            asm volatile("cp.async.wait_group 0;");
        }
        __syncthreads();

        const __half* Abuf = smh + s * (STAGE_B / 2);
        const __half* Bbuf = smh + (2 * STAGE_B + s * STAGE_B) / 2;

        #pragma unroll
        for (int ks = 0; ks < 2; ks++) {        // two k16 steps per 32-chunk
            const int koff = ks * 16 + tig * 2;
            uint32_t a[2][4];
            #pragma unroll
            for (int mi = 0; mi < 2; mi++) {
                int R = warp_m * 32 + mi * 16;
                a[mi][0] = *reinterpret_cast<const uint32_t*>(&Abuf[(R + gid) * SHW + koff]);
                a[mi][1] = *reinterpret_cast<const uint32_t*>(&Abuf[(R + gid + 8) * SHW + koff]);
                a[mi][2] = *reinterpret_cast<const uint32_t*>(&Abuf[(R + gid) * SHW + koff + 8]);
                a[mi][3] = *reinterpret_cast<const uint32_t*>(&Abuf[(R + gid + 8) * SHW + koff + 8]);
            }
            #pragma unroll
            for (int ni = 0; ni < 8; ni++) {
                int n0 = warp_n * 64 + ni * 8;
                uint32_t b0 = *reinterpret_cast<const uint32_t*>(&Bbuf[(n0 + gid) * SHW + koff]);
                uint32_t b1 = *reinterpret_cast<const uint32_t*>(&Bbuf[(n0 + gid) * SHW + koff + 8]);
                #pragma unroll
                for (int mi = 0; mi < 2; mi++) {
                    asm volatile(
                        "mma.sync.aligned.m16n8k16.row.col.f32.f16.f16.f32 "
                        "{%0,%1,%2,%3}, {%4,%5,%6,%7}, {%8,%9}, {%0,%1,%2,%3};"
                        : "+f"(acc[mi][ni][0]), "+f"(acc[mi][ni][1]),
                          "+f"(acc[mi][ni][2]), "+f"(acc[mi][ni][3])
                        : "r"(a[mi][0]), "r"(a[mi][1]), "r"(a[mi][2]), "r"(a[mi][3]),
                          "r"(b0), "r"(b1));
                }
            }
        }
        __syncthreads();
    }

    const bool half_out = (blockIdx.y != 0);
    #pragma unroll
    for (int mi = 0; mi < 2; mi++) {
        int r0 = tile0 + warp_m * 32 + mi * 16 + gid;
        #pragma unroll
        for (int ni = 0; ni < 8; ni++) {
            int c = warp_n * 64 + ni * 8 + tig * 2;
            if (half_out) {
                if (r0 < Nrows)
                    *reinterpret_cast<__half2*>(C1h + (size_t)r0 * 128 + c) =
                        __floats2half2_rn(acc[mi][ni][0], acc[mi][ni][1]);
                if (r0 + 8 < Nrows)
                    *reinterpret_cast<__half2*>(C1h + (size_t)(r0 + 8) * 128 + c) =
                        __floats2half2_rn(acc[mi][ni][2], acc[mi][ni][3]);
            } else {
                if (r0 < Nrows)
                    *reinterpret_cast<float2*>(C0 + (size_t)r0 * 128 + c) =
                        make_float2(acc[mi][ni][0], acc[mi][ni][1]);
                if (r0 + 8 < Nrows)
                    *reinterpret_cast<float2*>(C0 + (size_t)(r0 + 8) * 128 + c) =
                        make_float2(acc[mi][ni][2], acc[mi][ni][3]);
            }
        }
    }
}

// ---------------- CSR SpMM (fp16 gather), fp16 H output ---------------------
// H[r] = relu(Self[r] + (sum Ph[c]) * invdeg[r]) ; fp32 accumulate.
__global__ void spmm_relu_kernel(const __half* __restrict__ P,
                                 const float* __restrict__ S,
                                 __half* __restrict__ H)
{
    int warp = (blockIdx.x * blockDim.x + threadIdx.x) >> 5;
    int lane = threadIdx.x & 31;
    if (warp >= NNODES) return;
    int r = warp;
    int start = g_rowptr[r], end = g_rowptr[r + 1];

    float4 acc = make_float4(0.f, 0.f, 0.f, 0.f);
    for (int base = start; base < end; base += 32) {
        int idx = base + lane;
        int c = (idx < end) ? g_colidx[idx] : 0;
        int cnt = min(32, end - base);
        #pragma unroll 4
        for (int j = 0; j < cnt; j++) {
            int cj = __shfl_sync(0xffffffffu, c, j);
            uint2 raw = *reinterpret_cast<const uint2*>(P + (size_t)cj * 128 + lane * 4);
            float2 f0 = __half22float2(*reinterpret_cast<__half2*>(&raw.x));
            float2 f1 = __half22float2(*reinterpret_cast<__half2*>(&raw.y));
            acc.x += f0.x; acc.y += f0.y; acc.z += f1.x; acc.w += f1.y;
        }
    }
    float inv = g_invdeg[r];
    float4 s = *reinterpret_cast<const float4*>(S + (size_t)r * 128 + lane * 4);
    float hx = fmaxf(fmaf(acc.x, inv, s.x), 0.f);
    float hy = fmaxf(fmaf(acc.y, inv, s.y), 0.f);
    float hz = fmaxf(fmaf(acc.z, inv, s.z), 0.f);
    float hw = fmaxf(fmaf(acc.w, inv, s.w), 0.f);
    uint2 o;
    *reinterpret_cast<__half2*>(&o.x) = __floats2half2_rn(hx, hy);
    *reinterpret_cast<__half2*>(&o.y) = __floats2half2_rn(hz, hw);
    *reinterpret_cast<uint2*>(H + (size_t)r * 128 + lane * 4) = o;
}

// ---------------- Classifier GEMM (fp16 A) + bias + log_softmax -------------
__global__ __launch_bounds__(256, 2) void cls_kernel(
    const __half* __restrict__ A, const float* __restrict__ W,
    const float* __restrict__ bias, float* __restrict__ out, int Nrows)
{
    __shared__ float As[8][128];
    __shared__ float Bs[8][64];

    int tid = threadIdx.x;
    int n0 = blockIdx.x * 128;
    int tx = tid & 15, ty = tid >> 4;

    float acc[8][4];
    #pragma unroll
    for (int i = 0; i < 8; i++)
        #pragma unroll
        for (int j = 0; j < 4; j++) acc[i][j] = 0.f;

    int aRow = tid >> 1;
    int aCol = (tid & 1) * 4;
    bool aValid = (n0 + aRow) < Nrows;
    const __half* Aptr = A + (size_t)(n0 + aRow) * NHID + aCol;

    int bRow = tid >> 1;
    int bCol = (tid & 1) * 4;
    const float* Bptr = (tid < 128 && bRow < NCLASS) ? W + (size_t)bRow * NHID + bCol : nullptr;

    for (int k0 = 0; k0 < NHID; k0 += 8) {
        float2 f0 = make_float2(0.f, 0.f), f1 = make_float2(0.f, 0.f);
        if (aValid) {
            uint2 raw = *reinterpret_cast<const uint2*>(Aptr + k0);
            f0 = __half22float2(*reinterpret_cast<__half2*>(&raw.x));
            f1 = __half22float2(*reinterpret_cast<__half2*>(&raw.y));
        }
        As[aCol + 0][aRow] = f0.x; As[aCol + 1][aRow] = f0.y;
        As[aCol + 2][aRow] = f1.x; As[aCol + 3][aRow] = f1.y;
        if (tid < 128) {
            float4 bv = Bptr ? *reinterpret_cast<const float4*>(Bptr + k0)
                             : make_float4(0.f, 0.f, 0.f, 0.f);
            Bs[bCol + 0][bRow] = bv.x; Bs[bCol + 1][bRow] = bv.y;
            Bs[bCol + 2][bRow] = bv.z; Bs[bCol + 3][bRow] = bv.w;
        }
        __syncthreads();

        #pragma unroll
        for (int k = 0; k < 8; k++) {
            float a[8], b[4];
            *reinterpret_cast<float4*>(a)     = *reinterpret_cast<float4*>(&As[k][ty * 8]);
            *reinterpret_cast<float4*>(a + 4) = *reinterpret_cast<float4*>(&As[k][ty * 8 + 4]);
            *reinterpret_cast<float4*>(b)     = *reinterpret_cast<float4*>(&Bs[k][tx * 4]);
            #pragma unroll
            for (int i = 0; i < 8; i++)
                #pragma unroll
                for (int j = 0; j < 4; j++)
                    acc[i][j] = fmaf(a[i], b[j], acc[i][j]);
        }
        __syncthreads();
    }

    float bs[4];
    #pragma unroll
    for (int j = 0; j < 4; j++) {
        int c = tx * 4 + j;
        bs[j] = (c < NCLASS) ? bias[c] : 0.f;
    }

    #pragma unroll
    for (int i = 0; i < 8; i++) {
        int row = n0 + ty * 8 + i;
        float l[4];
        #pragma unroll
        for (int j = 0; j < 4; j++) {
            int c = tx * 4 + j;
            l[j] = (c < NCLASS) ? acc[i][j] + bs[j] : -INFINITY;
        }
        float mx = fmaxf(fmaxf(l[0], l[1]), fmaxf(l[2], l[3]));
        #pragma unroll
        for (int o = 8; o > 0; o >>= 1)
            mx = fmaxf(mx, __shfl_xor_sync(0xffffffffu, mx, o));
        float se = 0.f;
        #pragma unroll
        for (int j = 0; j < 4; j++) {
            int c = tx * 4 + j;
            if (c < NCLASS) se += __expf(l[j] - mx);
        }
        #pragma unroll
        for (int o = 8; o > 0; o >>= 1)
            se += __shfl_xor_sync(0xffffffffu, se, o);
        float ls = mx + __logf(se);
        if (row < Nrows) {
            #pragma unroll
            for (int j = 0; j < 4; j++) {
                int c = tx * 4 + j;
                if (c < NCLASS) out[(size_t)row * NCLASS + c] = l[j] - ls;
            }
        }
    }
}

// ---------------- launch ----------------
extern "C" void kernel_launch(void* const* d_in, const int* in_sizes, int n_in,
                              void* d_out, int out_size) {
    const float* x     = (const float*)d_in[0];   // [N,256]
    const float* W1    = (const float*)d_in[1];   // [128,512]
    const float* W2    = (const float*)d_in[2];   // [128,256]
    const float* mlpW  = (const float*)d_in[3];   // [40,128]
    const float* mlpb  = (const float*)d_in[4];   // [40]
    const int*   erow  = (const int*)d_in[5];
    const int*   ecol  = (const int*)d_in[6];
    int E = in_sizes[5];
    float* out = (float*)d_out;

    float* pSelf;
    __half *pPh, *pH, *pXh, *pW1h, *pW2h;
    cudaGetSymbolAddress((void**)&pSelf, g_Self);
    cudaGetSymbolAddress((void**)&pPh, g_Ph);
    cudaGetSymbolAddress((void**)&pH, g_H);
    cudaGetSymbolAddress((void**)&pXh, g_xh);
    cudaGetSymbolAddress((void**)&pW1h, g_W1h);
    cudaGetSymbolAddress((void**)&pW2h, g_W2h);

    static cudaStream_t s2 = nullptr;
    static cudaEvent_t  ev_fork = nullptr, ev_join = nullptr;
    if (s2 == nullptr) {
        cudaStreamCreateWithFlags(&s2, cudaStreamNonBlocking);
        cudaEventCreateWithFlags(&ev_fork, cudaEventDisableTiming);
        cudaEventCreateWithFlags(&ev_join, cudaEventDisableTiming);
        cudaFuncSetAttribute(mma_gemm_fp16,
                             cudaFuncAttributeMaxDynamicSharedMemorySize, GEMM_SMEM_BYTES);
    }

    const int nb_nodes = (NNODES + 255) / 256;
    const int nb_edges = (E + 255) / 256;
    const int nb_warps = (NNODES * 32 + 255) / 256;
    const int nb_tiles = (NNODES + 127) / 128;
    dim3 g1(nb_tiles, 2);

    // ---- Fork: converts + layer-1 GEMM on s2; CSR build on main ----
    cudaEventRecord(ev_fork, 0);
    cudaStreamWaitEvent(s2, ev_fork, 0);
    {
        int n4x = NNODES * NFEAT / 4;
        k_cvt<<<(n4x + 255) / 256, 256, 0, s2>>>(x, pXh, n4x);
        int n4w1 = NHID * 2 * NFEAT / 4;
        k_cvt<<<(n4w1 + 255) / 256, 256, 0, s2>>>(W1, pW1h, n4w1);
        int n4w2 = NHID * 2 * NHID / 4;
        k_cvt<<<(n4w2 + 255) / 256, 256, 0, s2>>>(W2, pW2h, n4w2);
        mma_gemm_fp16<<<g1, 256, GEMM_SMEM_BYTES, s2>>>(
            pXh, pW1h, NFEAT, 2 * NFEAT, pSelf, pPh, NNODES);
    }
    cudaEventRecord(ev_join, s2);

    k_zero_deg<<<nb_nodes, 256>>>();
    k_hist<<<nb_edges, 256>>>(erow, E);
    k_scan1<<<SCAN_NB, SCAN_B>>>();
    k_scan2<<<1, 128>>>();
    k_scan3<<<SCAN_NB, SCAN_B>>>();
    k_scatter<<<nb_edges, 256>>>(erow, ecol, E);

    // ---- Join: SpMM needs both CSR and the layer-1 projections ----
    cudaStreamWaitEvent(0, ev_join, 0);
    spmm_relu_kernel<<<nb_warps, 256>>>(pPh, pSelf, pH);

    // Layer 2 (A = H fp16)
    mma_gemm_fp16<<<g1, 256, GEMM_SMEM_BYTES>>>(
        pH, pW2h, NHID, 2 * NHID, pSelf, pPh, NNODES);
    spmm_relu_kernel<<<nb_warps, 256>>>(pPh, pSelf, pH);

    cls_kernel<<<nb_tiles, 256>>>(pH, mlpW, mlpb, out, NNODES);
}

// round 16
// speedup vs baseline: 1.9406x; 1.1076x over previous
#include <cuda_runtime.h>
#include <cuda_fp16.h>
#include <cstdint>
#include <math.h>

#define NNODES 100000
#define NEDGES 3200000
#define NFEAT  256
#define NHID   128
#define NCLASS 40

#define SCAN_B  1024
#define SCAN_NB ((NNODES + SCAN_B - 1) / SCAN_B)   // 98

// ---------------- scratch ----------------
__device__ float  g_Self[(size_t)NNODES * NHID];
__device__ __half g_Ph[(size_t)NNODES * NHID];      // neighbor projection, fp16
__device__ __half g_H[(size_t)NNODES * NHID];       // hidden activations, fp16
__device__ __half g_xh[(size_t)NNODES * NFEAT];     // fp16 copy of x
__device__ __half g_W1h[NHID * 2 * NFEAT];
__device__ __half g_W2h[NHID * 2 * NHID];
__device__ __half g_Wch[64 * NHID];                 // cls W, zero-padded to 64 rows
__device__ int    g_deg[NNODES];
__device__ int    g_rowptr[NNODES + 1];
__device__ int    g_cursor[NNODES];
__device__ int    g_colidx[NEDGES];
__device__ float  g_invdeg[NNODES];
__device__ int    g_blocksum[SCAN_NB];

// ---------------- fp32 -> fp16 convert (vectorized) ----------------
__global__ void k_cvt(const float* __restrict__ src, __half* __restrict__ dst, int n4) {
    int i = blockIdx.x * blockDim.x + threadIdx.x;
    if (i < n4) {
        float4 v = reinterpret_cast<const float4*>(src)[i];
        uint2 o;
        *reinterpret_cast<__half2*>(&o.x) = __floats2half2_rn(v.x, v.y);
        *reinterpret_cast<__half2*>(&o.y) = __floats2half2_rn(v.z, v.w);
        reinterpret_cast<uint2*>(dst)[i] = o;
    }
}

// cls W: fp16, rows 40..63 zeroed
__global__ void k_cvt_cls(const float* __restrict__ W) {
    int idx = blockIdx.x * blockDim.x + threadIdx.x;   // 64*128
    if (idx < 64 * NHID) {
        int r = idx >> 7, k = idx & 127;
        g_Wch[idx] = (r < NCLASS) ? __float2half(W[r * NHID + k]) : __half(0.f);
    }
}

// ---------------- CSR build ----------------
__global__ void k_zero_deg() {
    int i = blockIdx.x * blockDim.x + threadIdx.x;
    if (i < NNODES) g_deg[i] = 0;
}
__global__ void k_hist(const int* __restrict__ rows, int E) {
    int e = blockIdx.x * blockDim.x + threadIdx.x;
    if (e < E) atomicAdd(&g_deg[rows[e]], 1);
}

__global__ void k_scan1() {
    __shared__ int wsum[32];
    int tid = threadIdx.x, lane = tid & 31, wid = tid >> 5;
    int i = blockIdx.x * SCAN_B + tid;
    int v = (i < NNODES) ? g_deg[i] : 0;
    #pragma unroll
    for (int o = 16; o > 0; o >>= 1)
        v += __shfl_xor_sync(0xffffffffu, v, o);
    if (lane == 0) wsum[wid] = v;
    __syncthreads();
    if (wid == 0) {
        int y = wsum[lane];
        #pragma unroll
        for (int o = 16; o > 0; o >>= 1)
            y += __shfl_xor_sync(0xffffffffu, y, o);
        if (lane == 0) g_blocksum[blockIdx.x] = y;
    }
}

__global__ void k_scan2() {
    __shared__ int s[128];
    int tid = threadIdx.x;
    int v = (tid < SCAN_NB) ? g_blocksum[tid] : 0;
    s[tid] = v;
    __syncthreads();
    #pragma unroll
    for (int o = 1; o < 128; o <<= 1) {
        int t = (tid >= o) ? s[tid - o] : 0;
        __syncthreads();
        s[tid] += t;
        __syncthreads();
    }
    if (tid < SCAN_NB) g_blocksum[tid] = s[tid] - v;   // exclusive
    if (tid == 127) g_rowptr[NNODES] = s[127];
}

__global__ void k_scan3() {
    __shared__ int wsum[32];
    int tid = threadIdx.x, lane = tid & 31, wid = tid >> 5;
    int i = blockIdx.x * SCAN_B + tid;
    int v = (i < NNODES) ? g_deg[i] : 0;
    int x = v;
    #pragma unroll
    for (int o = 1; o < 32; o <<= 1) {
        int t = __shfl_up_sync(0xffffffffu, x, o);
        if (lane >= o) x += t;
    }
    if (lane == 31) wsum[wid] = x;
    __syncthreads();
    if (wid == 0) {
        int y = wsum[lane];
        #pragma unroll
        for (int o = 1; o < 32; o <<= 1) {
            int t = __shfl_up_sync(0xffffffffu, y, o);
            if (lane >= o) y += t;
        }
        wsum[lane] = y;
    }
    __syncthreads();
    if (i < NNODES) {
        int incl = x + (wid > 0 ? wsum[wid - 1] : 0) + g_blocksum[blockIdx.x];
        int excl = incl - v;
        g_rowptr[i] = excl;
        g_cursor[i] = excl;
        g_invdeg[i] = 1.0f / ((float)v + 1.0f);
    }
}

__global__ void k_scatter(const int* __restrict__ rows, const int* __restrict__ cols, int E) {
    int e = blockIdx.x * blockDim.x + threadIdx.x;
    if (e < E) {
        int r = rows[e];
        int p = atomicAdd(&g_cursor[r], 1);
        g_colidx[p] = cols[e];
    }
}

// ---------------- ldmatrix helper ----------------
__device__ __forceinline__ void ldsm4(uint32_t& r0, uint32_t& r1, uint32_t& r2,
                                      uint32_t& r3, uint32_t addr) {
    asm volatile("ldmatrix.sync.aligned.m8n8.x4.shared.b16 {%0,%1,%2,%3}, [%4];"
                 : "=r"(r0), "=r"(r1), "=r"(r2), "=r"(r3) : "r"(addr));
}

// ================= fp16 mma.sync m16n8k16 GEMM, ldmatrix fragments ==========
// y = blockIdx.y: 0 -> C0 fp32 (self slab of W), 1 -> C1h fp16 (neigh slab).
// smem rows: 32 halves data + 8 pad = 40 halves (80 B): ldmatrix phases
// conflict-free (banks 20r mod 32 distinct for r=0..7).
#define SHW 40                          // halves per smem row
#define SRB 80                          // bytes per smem row
#define STAGE_B (128 * SRB)             // 10240 bytes per stage (A or B)
#define GEMM_SMEM_BYTES (4 * STAGE_B)   // 40960

__global__ __launch_bounds__(256, 2) void mma_gemm_fp16(
    const __half* __restrict__ A, const __half* __restrict__ W,
    int K, int ldb,
    float* __restrict__ C0, __half* __restrict__ C1h, int Nrows)
{
    extern __shared__ char smem[];
    const int tid = threadIdx.x;
    const int lane = tid & 31, wid = tid >> 5;
    const int warp_m = wid & 3;
    const int warp_n = wid >> 2;
    const int gid = lane >> 2, tig = lane & 3;
    const int tile0 = blockIdx.x * 128;
    const __half* Bp = W + (size_t)blockIdx.y * K;
    const uint32_t smem_u32 = (uint32_t)__cvta_generic_to_shared(smem);
    // per-lane ldmatrix row offset: row (lane&15), k-half (lane>>4)*8 halves
    const uint32_t lm_off = (uint32_t)((lane & 15) * SRB + ((lane >> 4) << 4));

    float acc[2][8][4];
    #pragma unroll
    for (int mi = 0; mi < 2; mi++)
        #pragma unroll
        for (int ni = 0; ni < 8; ni++)
            #pragma unroll
            for (int q = 0; q < 4; q++) acc[mi][ni][q] = 0.f;

    const int srow = tid >> 2;          // +64 per it
    const int sc   = (tid & 3) << 3;    // halves offset within row

    auto stage = [&](int s, int kc) {
        #pragma unroll
        for (int it = 0; it < 2; it++) {
            int row = srow + (it << 6);
            int gr = tile0 + row;
            if (gr >= Nrows) gr = Nrows - 1;
            const __half* ga = A + (size_t)gr * K + kc + sc;
            uint32_t da = smem_u32 + (uint32_t)(s * STAGE_B + row * SRB + sc * 2);
            asm volatile("cp.async.ca.shared.global [%0], [%1], 16;" :: "r"(da), "l"(ga));
            const __half* gb = Bp + (size_t)row * ldb + kc + sc;
            uint32_t db = smem_u32 + (uint32_t)(2 * STAGE_B + s * STAGE_B + row * SRB + sc * 2);
            asm volatile("cp.async.ca.shared.global [%0], [%1], 16;" :: "r"(db), "l"(gb));
        }
        asm volatile("cp.async.commit_group;");
    };

    const int nch = K >> 5;
    stage(0, 0);

    for (int ch = 0; ch < nch; ch++) {
        const int s = ch & 1;
        if (ch + 1 < nch) {
            stage(s ^ 1, (ch + 1) << 5);
            asm volatile("cp.async.wait_group 1;");
        } else {
            asm volatile("cp.async.wait_group 0;");
        }
        __syncthreads();

        const uint32_t abase = smem_u32 + s * STAGE_B + lm_off;
        const uint32_t bbase = smem_u32 + 2 * STAGE_B + s * STAGE_B + lm_off;

        #pragma unroll
        for (int ks = 0; ks < 2; ks++) {        // two k16 steps per 32-chunk
            const uint32_t koffb = ks * 32;     // bytes: 16 halves
            uint32_t a[2][4];
            #pragma unroll
            for (int mi = 0; mi < 2; mi++)
                ldsm4(a[mi][0], a[mi][1], a[mi][2], a[mi][3],
                      abase + (uint32_t)((warp_m * 32 + mi * 16) * SRB) + koffb);
            uint32_t b[8][2];
            #pragma unroll
            for (int g = 0; g < 4; g++) {
                uint32_t r0, r1, r2, r3;
                ldsm4(r0, r1, r2, r3,
                      bbase + (uint32_t)((warp_n * 64 + g * 16) * SRB) + koffb);
                b[2 * g][0] = r0; b[2 * g + 1][0] = r1;
                b[2 * g][1] = r2; b[2 * g + 1][1] = r3;
            }
            #pragma unroll
            for (int ni = 0; ni < 8; ni++)
                #pragma unroll
                for (int mi = 0; mi < 2; mi++) {
                    asm volatile(
                        "mma.sync.aligned.m16n8k16.row.col.f32.f16.f16.f32 "
                        "{%0,%1,%2,%3}, {%4,%5,%6,%7}, {%8,%9}, {%0,%1,%2,%3};"
                        : "+f"(acc[mi][ni][0]), "+f"(acc[mi][ni][1]),
                          "+f"(acc[mi][ni][2]), "+f"(acc[mi][ni][3])
                        : "r"(a[mi][0]), "r"(a[mi][1]), "r"(a[mi][2]), "r"(a[mi][3]),
                          "r"(b[ni][0]), "r"(b[ni][1]));
                }
        }
        __syncthreads();
    }

    const bool half_out = (blockIdx.y != 0);
    #pragma unroll
    for (int mi = 0; mi < 2; mi++) {
        int r0 = tile0 + warp_m * 32 + mi * 16 + gid;
        #pragma unroll
        for (int ni = 0; ni < 8; ni++) {
            int c = warp_n * 64 + ni * 8 + tig * 2;
            if (half_out) {
                if (r0 < Nrows)
                    *reinterpret_cast<__half2*>(C1h + (size_t)r0 * 128 + c) =
                        __floats2half2_rn(acc[mi][ni][0], acc[mi][ni][1]);
                if (r0 + 8 < Nrows)
                    *reinterpret_cast<__half2*>(C1h + (size_t)(r0 + 8) * 128 + c) =
                        __floats2half2_rn(acc[mi][ni][2], acc[mi][ni][3]);
            } else {
                if (r0 < Nrows)
                    *reinterpret_cast<float2*>(C0 + (size_t)r0 * 128 + c) =
                        make_float2(acc[mi][ni][0], acc[mi][ni][1]);
                if (r0 + 8 < Nrows)
                    *reinterpret_cast<float2*>(C0 + (size_t)(r0 + 8) * 128 + c) =
                        make_float2(acc[mi][ni][2], acc[mi][ni][3]);
            }
        }
    }
}

// ---------------- CSR SpMM (fp16 gather), fp16 H output ---------------------
__global__ void spmm_relu_kernel(const __half* __restrict__ P,
                                 const float* __restrict__ S,
                                 __half* __restrict__ H)
{
    int warp = (blockIdx.x * blockDim.x + threadIdx.x) >> 5;
    int lane = threadIdx.x & 31;
    if (warp >= NNODES) return;
    int r = warp;
    int start = g_rowptr[r], end = g_rowptr[r + 1];

    float4 acc = make_float4(0.f, 0.f, 0.f, 0.f);
    for (int base = start; base < end; base += 32) {
        int idx = base + lane;
        int c = (idx < end) ? g_colidx[idx] : 0;
        int cnt = min(32, end - base);
        #pragma unroll 4
        for (int j = 0; j < cnt; j++) {
            int cj = __shfl_sync(0xffffffffu, c, j);
            uint2 raw = *reinterpret_cast<const uint2*>(P + (size_t)cj * 128 + lane * 4);
            float2 f0 = __half22float2(*reinterpret_cast<__half2*>(&raw.x));
            float2 f1 = __half22float2(*reinterpret_cast<__half2*>(&raw.y));
            acc.x += f0.x; acc.y += f0.y; acc.z += f1.x; acc.w += f1.y;
        }
    }
    float inv = g_invdeg[r];
    float4 s = *reinterpret_cast<const float4*>(S + (size_t)r * 128 + lane * 4);
    float hx = fmaxf(fmaf(acc.x, inv, s.x), 0.f);
    float hy = fmaxf(fmaf(acc.y, inv, s.y), 0.f);
    float hz = fmaxf(fmaf(acc.z, inv, s.z), 0.f);
    float hw = fmaxf(fmaf(acc.w, inv, s.w), 0.f);
    uint2 o;
    *reinterpret_cast<__half2*>(&o.x) = __floats2half2_rn(hx, hy);
    *reinterpret_cast<__half2*>(&o.y) = __floats2half2_rn(hz, hw);
    *reinterpret_cast<uint2*>(H + (size_t)r * 128 + lane * 4) = o;
}

// ====== Classifier: fp16 mma (clone of layer GEMM) + fused log_softmax ======
// Tile 128 rows x 64 cols; K=128. B (padded W, 64x128 fp16) loaded once to
// smem with 136-half rows (272 B: banks 4r mod 32 distinct -> conflict-free).
// Logits staged to smem (aliases A stages), softmax warp-per-16-rows.
#define CLS_BW   136
#define CLS_B_OFF (2 * STAGE_B)                       // 20480
#define CLS_SMEM (CLS_B_OFF + 64 * CLS_BW * 2)        // 37888 >= logits 34816

__global__ __launch_bounds__(256, 2) void cls_mma2(
    const __half* __restrict__ A, const float* __restrict__ bias,
    float* __restrict__ out, int Nrows)
{
    extern __shared__ char smem[];
    float* logits = reinterpret_cast<float*>(smem);    // [128][68], alias A+B
    const int tid = threadIdx.x;
    const int lane = tid & 31, wid = tid >> 5;
    const int warp_m = wid & 3;
    const int warp_n = wid >> 2;                       // 0..1 -> 32 cols
    const int gid = lane >> 2, tig = lane & 3;
    const int tile0 = blockIdx.x * 128;
    const uint32_t smem_u32 = (uint32_t)__cvta_generic_to_shared(smem);
    const uint32_t lm_offA = (uint32_t)((lane & 15) * SRB + ((lane >> 4) << 4));
    const uint32_t lm_offB = (uint32_t)((lane & 15) * (CLS_BW * 2) + ((lane >> 4) << 4));

    // load full padded W into smem (64 rows x 16 chunks of 8 halves)
    {
        const uint4* gW = reinterpret_cast<const uint4*>(g_Wch);
        for (int i = tid; i < 64 * 16; i += 256) {
            int r = i >> 4, q = i & 15;
            *reinterpret_cast<uint4*>(smem + CLS_B_OFF + (r * CLS_BW + q * 8) * 2) = gW[i];
        }
    }

    float acc[2][4][4];
    #pragma unroll
    for (int mi = 0; mi < 2; mi++)
        #pragma unroll
        for (int ni = 0; ni < 4; ni++)
            #pragma unroll
            for (int q = 0; q < 4; q++) acc[mi][ni][q] = 0.f;

    const int srow = tid >> 2;
    const int sc   = (tid & 3) << 3;

    auto stageA = [&](int s, int kc) {
        #pragma unroll
        for (int it = 0; it < 2; it++) {
            int row = srow + (it << 6);
            int gr = tile0 + row;
            if (gr >= Nrows) gr = Nrows - 1;
            const __half* ga = A + (size_t)gr * NHID + kc + sc;
            uint32_t da = smem_u32 + (uint32_t)(s * STAGE_B + row * SRB + sc * 2);
            asm volatile("cp.async.ca.shared.global [%0], [%1], 16;" :: "r"(da), "l"(ga));
        }
        asm volatile("cp.async.commit_group;");
    };

    stageA(0, 0);
    __syncthreads();   // covers the W smem fill too (before first B use)

    #pragma unroll
    for (int ch = 0; ch < 4; ch++) {                   // K = 128
        const int s = ch & 1;
        if (ch + 1 < 4) {
            stageA(s ^ 1, (ch + 1) << 5);
            asm volatile("cp.async.wait_group 1;");
        } else {
            asm volatile("cp.async.wait_group 0;");
        }
        __syncthreads();

        const uint32_t abase = smem_u32 + s * STAGE_B + lm_offA;
        const uint32_t bbase = smem_u32 + CLS_B_OFF + lm_offB + (uint32_t)(ch * 64);

        #pragma unroll
        for (int ks = 0; ks < 2; ks++) {
            const uint32_t koffb = ks * 32;
            uint32_t a[2][4];
            #pragma unroll
            for (int mi = 0; mi < 2; mi++)
                ldsm4(a[mi][0], a[mi][1], a[mi][2], a[mi][3],
                      abase + (uint32_t)((warp_m * 32 + mi * 16) * SRB) + koffb);
            uint32_t b[4][2];
            #pragma unroll
            for (int g = 0; g < 2; g++) {
                uint32_t r0, r1, r2, r3;
                ldsm4(r0, r1, r2, r3,
                      bbase + (uint32_t)((warp_n * 32 + g * 16) * (CLS_BW * 2)) + koffb);
                b[2 * g][0] = r0; b[2 * g + 1][0] = r1;
                b[2 * g][1] = r2; b[2 * g + 1][1] = r3;
            }
            #pragma unroll
            for (int ni = 0; ni < 4; ni++)
                #pragma unroll
                for (int mi = 0; mi < 2; mi++) {
                    asm volatile(
                        "mma.sync.aligned.m16n8k16.row.col.f32.f16.f16.f32 "
                        "{%0,%1,%2,%3}, {%4,%5,%6,%7}, {%8,%9}, {%0,%1,%2,%3};"
                        : "+f"(acc[mi][ni][0]), "+f"(acc[mi][ni][1]),
                          "+f"(acc[mi][ni][2]), "+f"(acc[mi][ni][3])
                        : "r"(a[mi][0]), "r"(a[mi][1]), "r"(a[mi][2]), "r"(a[mi][3]),
                          "r"(b[ni][0]), "r"(b[ni][1]));
                }
        }
        __syncthreads();
    }

    // stage logits to smem [128][68] (aliases staging buffers; mainloop done)
    #pragma unroll
    for (int mi = 0; mi < 2; mi++) {
        int r0 = warp_m * 32 + mi * 16 + gid;
        #pragma unroll
        for (int ni = 0; ni < 4; ni++) {
            int c = warp_n * 32 + ni * 8 + tig * 2;
            *reinterpret_cast<float2*>(&logits[r0 * 68 + c]) =
                make_float2(acc[mi][ni][0], acc[mi][ni][1]);
            *reinterpret_cast<float2*>(&logits[(r0 + 8) * 68 + c]) =
                make_float2(acc[mi][ni][2], acc[mi][ni][3]);
        }
    }
    __syncthreads();

    // softmax: warp wid handles rows wid*16 .. +16
    const float b1 = bias[lane < NCLASS ? lane : 0];
    const float b2 = (lane < NCLASS - 32) ? bias[32 + lane] : 0.f;
    for (int t = 0; t < 16; t++) {
        int row = wid * 16 + t;
        int node = tile0 + row;
        if (node >= Nrows) break;
        float l1 = logits[row * 68 + lane] + b1;
        float l2 = (lane < NCLASS - 32) ? logits[row * 68 + 32 + lane] + b2 : -INFINITY;
        float mx = fmaxf(l1, l2);
        #pragma unroll
        for (int o = 16; o > 0; o >>= 1)
            mx = fmaxf(mx, __shfl_xor_sync(0xffffffffu, mx, o));
        float se = __expf(l1 - mx) + ((lane < NCLASS - 32) ? __expf(l2 - mx) : 0.f);
        #pragma unroll
        for (int o = 16; o > 0; o >>= 1)
            se += __shfl_xor_sync(0xffffffffu, se, o);
        float ls = mx + __logf(se);
        float* orow = out + (size_t)node * NCLASS;
        orow[lane] = l1 - ls;
        if (lane < NCLASS - 32) orow[32 + lane] = l2 - ls;
    }
}

// ---------------- launch ----------------
extern "C" void kernel_launch(void* const* d_in, const int* in_sizes, int n_in,
                              void* d_out, int out_size) {
    const float* x     = (const float*)d_in[0];   // [N,256]
    const float* W1    = (const float*)d_in[1];   // [128,512]
    const float* W2    = (const float*)d_in[2];   // [128,256]
    const float* mlpW  = (const float*)d_in[3];   // [40,128]
    const float* mlpb  = (const float*)d_in[4];   // [40]
    const int*   erow  = (const int*)d_in[5];
    const int*   ecol  = (const int*)d_in[6];
    int E = in_sizes[5];
    float* out = (float*)d_out;

    float* pSelf;
    __half *pPh, *pH, *pXh, *pW1h, *pW2h;
    cudaGetSymbolAddress((void**)&pSelf, g_Self);
    cudaGetSymbolAddress((void**)&pPh, g_Ph);
    cudaGetSymbolAddress((void**)&pH, g_H);
    cudaGetSymbolAddress((void**)&pXh, g_xh);
    cudaGetSymbolAddress((void**)&pW1h, g_W1h);
    cudaGetSymbolAddress((void**)&pW2h, g_W2h);

    static cudaStream_t s2 = nullptr;
    static cudaEvent_t  ev_fork = nullptr, ev_join = nullptr;
    if (s2 == nullptr) {
        cudaStreamCreateWithFlags(&s2, cudaStreamNonBlocking);
        cudaEventCreateWithFlags(&ev_fork, cudaEventDisableTiming);
        cudaEventCreateWithFlags(&ev_join, cudaEventDisableTiming);
        cudaFuncSetAttribute(mma_gemm_fp16,
                             cudaFuncAttributeMaxDynamicSharedMemorySize, GEMM_SMEM_BYTES);
        cudaFuncSetAttribute(cls_mma2,
                             cudaFuncAttributeMaxDynamicSharedMemorySize, CLS_SMEM);
    }

    const int nb_nodes = (NNODES + 255) / 256;
    const int nb_edges = (E + 255) / 256;
    const int nb_warps = (NNODES * 32 + 255) / 256;
    const int nb_tiles = (NNODES + 127) / 128;
    dim3 g1(nb_tiles, 2);

    // ---- Fork: converts + layer-1 GEMM on s2; CSR build on main ----
    cudaEventRecord(ev_fork, 0);
    cudaStreamWaitEvent(s2, ev_fork, 0);
    {
        int n4x = NNODES * NFEAT / 4;
        k_cvt<<<(n4x + 255) / 256, 256, 0, s2>>>(x, pXh, n4x);
        int n4w1 = NHID * 2 * NFEAT / 4;
        k_cvt<<<(n4w1 + 255) / 256, 256, 0, s2>>>(W1, pW1h, n4w1);
        int n4w2 = NHID * 2 * NHID / 4;
        k_cvt<<<(n4w2 + 255) / 256, 256, 0, s2>>>(W2, pW2h, n4w2);
        k_cvt_cls<<<(64 * NHID + 255) / 256, 256, 0, s2>>>(mlpW);
        mma_gemm_fp16<<<g1, 256, GEMM_SMEM_BYTES, s2>>>(
            pXh, pW1h, NFEAT, 2 * NFEAT, pSelf, pPh, NNODES);
    }
    cudaEventRecord(ev_join, s2);

    k_zero_deg<<<nb_nodes, 256>>>();
    k_hist<<<nb_edges, 256>>>(erow, E);
    k_scan1<<<SCAN_NB, SCAN_B>>>();
    k_scan2<<<1, 128>>>();
    k_scan3<<<SCAN_NB, SCAN_B>>>();
    k_scatter<<<nb_edges, 256>>>(erow, ecol, E);

    // ---- Join: SpMM needs both CSR and the layer-1 projections ----
    cudaStreamWaitEvent(0, ev_join, 0);
    spmm_relu_kernel<<<nb_warps, 256>>>(pPh, pSelf, pH);

    // Layer 2 (A = H fp16)
    mma_gemm_fp16<<<g1, 256, GEMM_SMEM_BYTES>>>(
        pH, pW2h, NHID, 2 * NHID, pSelf, pPh, NNODES);
    spmm_relu_kernel<<<nb_warps, 256>>>(pPh, pSelf, pH);

    cls_mma2<<<nb_tiles, 256, CLS_SMEM>>>(pH, mlpb, out, NNODES);
}